// round 11
// baseline (speedup 1.0000x reference)
#include <cuda_runtime.h>
#include <cuda_bf16.h>

// Problem constants
#define BB   32
#define HH   64
#define WW   64
#define NPIX (HH*WW)              // 4096 per image
#define NP   (BB*NPIX)            // 131072 pixels

// -------- scratch (device globals; no runtime allocation) --------
__device__ __nv_bfloat16 g_qkv[NP * 384]; // [0:192) local qkv (fc2), [192:384) global qkv (fc1)
__device__ float g_kp [BB*4*64*16];       // pooled global k: ((b*4+gh)*64+m)*16+cg
__device__ float g_vp [BB*4*64*16];       // pooled global v
__device__ __nv_bfloat16 g_xc [NP * 128]; // concat [xl | xg], pixel-major, bf16

// -------- packed fp32x2 helpers (sm_103a FFMA2 via PTX) --------
__device__ __forceinline__ void ffma2(unsigned long long& d,
                                      unsigned long long a, unsigned long long b) {
    asm("fma.rn.f32x2 %0, %1, %2, %0;" : "+l"(d) : "l"(a), "l"(b));
}
__device__ __forceinline__ unsigned long long fmul2(unsigned long long a,
                                                    unsigned long long b) {
    unsigned long long r;
    asm("mul.rn.f32x2 %0, %1, %2;" : "=l"(r) : "l"(a), "l"(b));
    return r;
}
__device__ __forceinline__ unsigned long long pack2(float lo, float hi) {
    unsigned long long r;
    asm("mov.b64 %0, {%1, %2};" : "=l"(r) : "f"(lo), "f"(hi));
    return r;
}
__device__ __forceinline__ float hadd2(unsigned long long v) {
    float lo, hi;
    asm("mov.b64 {%0, %1}, %2;" : "=f"(lo), "=f"(hi) : "l"(v));
    return lo + hi;
}
__device__ __forceinline__ void unpack2(unsigned long long v, float& lo, float& hi) {
    asm("mov.b64 {%0, %1}, %2;" : "=f"(lo), "=f"(hi) : "l"(v));
}

// -------- tensor-core helpers (mma.sync bf16) --------
__device__ __forceinline__ void ldsm_x4(unsigned addr, unsigned& r0, unsigned& r1,
                                        unsigned& r2, unsigned& r3) {
    asm volatile("ldmatrix.sync.aligned.m8n8.x4.shared.b16 {%0,%1,%2,%3}, [%4];"
                 : "=r"(r0), "=r"(r1), "=r"(r2), "=r"(r3) : "r"(addr));
}
__device__ __forceinline__ void mma16816(float* c, const unsigned* a,
                                         unsigned b0, unsigned b1) {
    asm volatile(
        "mma.sync.aligned.m16n8k16.row.col.f32.bf16.bf16.f32 "
        "{%0,%1,%2,%3}, {%4,%5,%6,%7}, {%8,%9}, {%0,%1,%2,%3};"
        : "+f"(c[0]), "+f"(c[1]), "+f"(c[2]), "+f"(c[3])
        : "r"(a[0]), "r"(a[1]), "r"(a[2]), "r"(a[3]), "r"(b0), "r"(b1));
}

// ============================================================================
// K1: fused LayerNorm + qkv GEMM.  (identical to 528.7us run)
// ============================================================================
__global__ __launch_bounds__(256) void lnqkv_kernel(
    const float* __restrict__ x, const float* __restrict__ gamma,
    const float* __restrict__ beta,
    const float* __restrict__ fc1_w, const float* __restrict__ fc1_b,
    const float* __restrict__ fc2_w, const float* __restrict__ fc2_b)
{
    extern __shared__ float dynsh[];
    float* As0   = dynsh;                 // local half  (c 0..63)
    float* As1   = dynsh + 4160;          // global half (c 64..127)
    float* s_raw = dynsh + 8320;          // [c*65 + pix]
    float* Ws    = s_raw;                 // alias; s_raw dead before first use
    __shared__ float smean[64], srstd[64];

    int P0   = blockIdx.x * 64;
    int bimg = P0 >> 12;
    int hw0  = P0 & 4095;
    const float* xb = x + (size_t)bimg * 128 * NPIX + hw0;

    for (int idx = threadIdx.x; idx < 8192; idx += 256) {
        int c = idx >> 6, pix = idx & 63;
        s_raw[c * 65 + pix] = xb[c * NPIX + pix];
    }
    __syncthreads();
    if (threadIdx.x < 64) {
        float sum = 0.f, sq = 0.f;
        #pragma unroll
        for (int c = 0; c < 128; c++) {
            float v = s_raw[c * 65 + threadIdx.x];
            sum += v; sq += v * v;
        }
        float m   = sum * (1.f / 128.f);
        float var = sq  * (1.f / 128.f) - m * m;
        smean[threadIdx.x] = m;
        srstd[threadIdx.x] = rsqrtf(var + 1e-5f);
    }
    __syncthreads();
    for (int idx = threadIdx.x; idx < 4096; idx += 256) {
        int pix = idx & 63, c2 = idx >> 6;     // c2 in [0,64)
        int c   = c2 * 2;
        float m = smean[pix], r = srstd[pix];
        float v0 = (s_raw[c * 65 + pix]       - m) * r * gamma[c]     + beta[c];
        float v1 = (s_raw[(c + 1) * 65 + pix] - m) * r * gamma[c + 1] + beta[c + 1];
        float* dst = (c2 < 32) ? As0 : As1;
        int k2 = c2 & 31;
        *(float2*)&dst[k2 * 130 + pix * 2] = make_float2(v0, v1);
    }
    __syncthreads();   // s_raw fully consumed; Ws may now overwrite it

    int tx = threadIdx.x & 15, ty = threadIdx.x >> 4;

    for (int nt = 0; nt < 6; nt++) {
        const float* W    = (nt < 3) ? fc2_w : fc1_w;
        const float* bias = (nt < 3) ? fc2_b : fc1_b;
        const float* As   = (nt < 3) ? As0   : As1;
        int wrow0 = (nt < 3) ? nt * 64 : (nt - 3) * 64;

        for (int u = threadIdx.x; u < 2048; u += 256) {
            int j = u >> 5, kk = u & 31;
            float2 w = *(const float2*)&W[(wrow0 + j) * 64 + kk * 2];
            *(float2*)&Ws[kk * 130 + j * 2] = w;
        }
        __syncthreads();

        unsigned long long acc2[4][4];
        #pragma unroll
        for (int i = 0; i < 4; i++)
            #pragma unroll
            for (int j = 0; j < 4; j++) acc2[i][j] = 0ULL;

        #pragma unroll 8
        for (int k2 = 0; k2 < 32; k2++) {
            unsigned long long a2[4], w2[4];
            #pragma unroll
            for (int i = 0; i < 4; i++)
                a2[i] = *(const unsigned long long*)&As[k2 * 130 + (tx + 16 * i) * 2];
            #pragma unroll
            for (int j = 0; j < 4; j++)
                w2[j] = *(const unsigned long long*)&Ws[k2 * 130 + (ty * 4 + j) * 2];
            #pragma unroll
            for (int i = 0; i < 4; i++)
                #pragma unroll
                for (int j = 0; j < 4; j++)
                    ffma2(acc2[i][j], a2[i], w2[j]);
        }

        float b0 = bias[wrow0 + ty * 4 + 0];
        float b1 = bias[wrow0 + ty * 4 + 1];
        float b2 = bias[wrow0 + ty * 4 + 2];
        float b3 = bias[wrow0 + ty * 4 + 3];
        #pragma unroll
        for (int i = 0; i < 4; i++) {
            float v0 = hadd2(acc2[i][0]) + b0;
            float v1 = hadd2(acc2[i][1]) + b1;
            float v2 = hadd2(acc2[i][2]) + b2;
            float v3 = hadd2(acc2[i][3]) + b3;
            __nv_bfloat162 p01 = __floats2bfloat162_rn(v0, v1);
            __nv_bfloat162 p23 = __floats2bfloat162_rn(v2, v3);
            uint2 o;
            o.x = *(unsigned int*)&p01;
            o.y = *(unsigned int*)&p23;
            *(uint2*)&g_qkv[(size_t)(P0 + tx + 16 * i) * 384 + nt * 64 + ty * 4] = o;
        }
        __syncthreads();
    }
}

// ============================================================================
// K2: 8x8 average pooling of global k,v (bf16 in, fp32 out).
// ============================================================================
__global__ __launch_bounds__(128) void pool_kernel()
{
    int bm = blockIdx.x;
    int b  = bm >> 6, m = bm & 63;
    int ph = m >> 3,  pw = m & 7;
    int t  = threadIdx.x;
    int base = b * NPIX + ph * 8 * WW + pw * 8;
    float acc = 0.f;
    #pragma unroll 8
    for (int i = 0; i < 64; i++) {
        int dy = i >> 3, dx = i & 7;
        acc += __bfloat162float(g_qkv[(size_t)(base + dy * WW + dx) * 384 + 256 + t]);
    }
    acc *= (1.f / 64.f);
    int gh = (t & 63) >> 4, cg = t & 15;
    float* dst = (t < 64) ? g_kp : g_vp;
    dst[((b * 4 + gh) * 64 + m) * 16 + cg] = acc;
}

// ============================================================================
// K3: global attention.  (identical to 528.7us run)
// ============================================================================
__global__ __launch_bounds__(256) void attn_kernel()
{
    __shared__ __align__(16) float sk[64 * 16], sv[64 * 16];
    int b = blockIdx.x >> 2, gh = blockIdx.x & 3;
    int kvbase = ((b * 4 + gh) * 64) * 16;
    for (int idx = threadIdx.x; idx < 1024; idx += 256) {
        sk[idx] = g_kp[kvbase + idx];
        sv[idx] = g_vp[kvbase + idx];
    }
    __syncthreads();

    int n = blockIdx.y * 256 + threadIdx.x;
    size_t p = (size_t)b * NPIX + n;
    const __nv_bfloat16* qp = g_qkv + p * 384 + 192 + gh * 16;
    uint4 qa = *(const uint4*)qp;
    uint4 qb = *(const uint4*)(qp + 8);
    unsigned int qw[8] = {qa.x, qa.y, qa.z, qa.w, qb.x, qb.y, qb.z, qb.w};
    unsigned long long q2[8];
    #pragma unroll
    for (int i = 0; i < 8; i++) {
        __nv_bfloat162 h = *(__nv_bfloat162*)&qw[i];
        float2 f = __bfloat1622float2(h);
        q2[i] = pack2(f.x, f.y);
    }

    float lo[64];
    float mx = -1e30f;
    #pragma unroll
    for (int m = 0; m < 64; m++) {
        unsigned long long acc2 = 0ULL;
        #pragma unroll
        for (int c4 = 0; c4 < 4; c4++) {
            ulonglong2 kk = *(const ulonglong2*)&sk[m * 16 + c4 * 4];
            ffma2(acc2, q2[c4 * 2],     kk.x);
            ffma2(acc2, q2[c4 * 2 + 1], kk.y);
        }
        float d = hadd2(acc2) * 0.125f;
        lo[m] = d;
        mx = fmaxf(mx, d);
    }
    float s = 0.f;
    #pragma unroll
    for (int m = 0; m < 64; m++) { float e = __expf(lo[m] - mx); lo[m] = e; s += e; }
    float inv = 1.f / s;

    unsigned long long o2[8];
    #pragma unroll
    for (int c2 = 0; c2 < 8; c2++) o2[c2] = 0ULL;
    #pragma unroll
    for (int m = 0; m < 64; m++) {
        float w = lo[m] * inv;
        unsigned long long ww = pack2(w, w);
        #pragma unroll
        for (int c4 = 0; c4 < 4; c4++) {
            ulonglong2 vv = *(const ulonglong2*)&sv[m * 16 + c4 * 4];
            ffma2(o2[c4 * 2],     ww, vv.x);
            ffma2(o2[c4 * 2 + 1], ww, vv.y);
        }
    }
    unsigned int ow[8];
    #pragma unroll
    for (int c2 = 0; c2 < 8; c2++) {
        float x0, x1;
        unpack2(o2[c2], x0, x1);
        __nv_bfloat162 h = __floats2bfloat162_rn(x0, x1);
        ow[c2] = *(unsigned int*)&h;
    }
    __nv_bfloat16* dst = g_xc + p * 128 + 64 + gh * 16;
    *(uint4*)dst       = make_uint4(ow[0], ow[1], ow[2], ow[3]);
    *(uint4*)(dst + 8) = make_uint4(ow[4], ow[5], ow[6], ow[7]);
}

// ============================================================================
// K4: local branch.  (identical to 528.7us run)
// ============================================================================
#define HP 9                       // float2 pitch per halo pixel
#define HQ_OFF 0
#define HK_OFF 2916
#define AB_OFF 5832
#define LOC_SMEM_F2 8136           // total float2s

__device__ __forceinline__ void dwconv8(
    const float2* __restrict__ h, const unsigned long long* __restrict__ w2,
    unsigned long long bias2, int tx, int c2, int ybase,
    unsigned long long out[8])
{
    unsigned long long r[3][3];
    #pragma unroll
    for (int rr = 0; rr < 2; rr++)
        #pragma unroll
        for (int dx = 0; dx < 3; dx++)
            r[rr + 1][dx] = *(const unsigned long long*)
                &h[((ybase + rr) * 18 + tx + dx) * HP + c2];
    #pragma unroll
    for (int yy = 0; yy < 8; yy++) {
        #pragma unroll
        for (int dx = 0; dx < 3; dx++) { r[0][dx] = r[1][dx]; r[1][dx] = r[2][dx]; }
        #pragma unroll
        for (int dx = 0; dx < 3; dx++)
            r[2][dx] = *(const unsigned long long*)
                &h[((ybase + yy + 2) * 18 + tx + dx) * HP + c2];
        unsigned long long acc = bias2;
        #pragma unroll
        for (int dy = 0; dy < 3; dy++)
            #pragma unroll
            for (int dx = 0; dx < 3; dx++)
                ffma2(acc, r[dy][dx], w2[dy * 3 + dx]);
        out[yy] = acc;
    }
}

__global__ __launch_bounds__(256) void local_kernel(
    const float* __restrict__ qconv_w, const float* __restrict__ qconv_b,
    const float* __restrict__ kconv_w, const float* __restrict__ kconv_b,
    const float* __restrict__ vconv_w, const float* __restrict__ vconv_b,
    const float* __restrict__ fc3_w,  const float* __restrict__ fc3_b,
    const float* __restrict__ fc4_w,  const float* __restrict__ fc4_b)
{
    extern __shared__ float2 lsm[];
    float2* hq   = lsm + HQ_OFF;     // q halo; later v halo
    float2* hk   = lsm + HK_OFF;     // k halo; later output staging
    float2* abuf = lsm + AB_OFF;     // a / gate buffer, [pix*HP + c2]

    __shared__ float2 swq[72], swk[72], swv[72];     // packed dwconv weights
    __shared__ float2 sbq[8],  sbk[8],  sbv[8];
    __shared__ float2 sw3[128], sw4[128];            // fc3/fc4 packed over input pairs
    __shared__ float  sb3[16],  sb4[16];

    int t    = threadIdx.x;
    int tile = blockIdx.x, lh = blockIdx.y, b = blockIdx.z;
    int y0 = (tile >> 2) * 16, x0 = (tile & 3) * 16;
    int jbase = lh * 16;

    for (int u = t; u < 72; u += 256) {
        int c2 = u / 9, tap = u - c2 * 9;
        swq[u] = make_float2(qconv_w[(2 * c2) * 9 + tap], qconv_w[(2 * c2 + 1) * 9 + tap]);
        swk[u] = make_float2(kconv_w[(2 * c2) * 9 + tap], kconv_w[(2 * c2 + 1) * 9 + tap]);
        swv[u] = make_float2(vconv_w[(2 * c2) * 9 + tap], vconv_w[(2 * c2 + 1) * 9 + tap]);
    }
    if (t < 8) {
        sbq[t] = make_float2(qconv_b[2 * t], qconv_b[2 * t + 1]);
        sbk[t] = make_float2(kconv_b[2 * t], kconv_b[2 * t + 1]);
        sbv[t] = make_float2(vconv_b[2 * t], vconv_b[2 * t + 1]);
    }
    for (int u = t; u < 128; u += 256) {
        int o = u >> 3, i2 = u & 7;
        sw3[u] = make_float2(fc3_w[o * 16 + 2 * i2], fc3_w[o * 16 + 2 * i2 + 1]);
        sw4[u] = make_float2(fc4_w[o * 16 + 2 * i2], fc4_w[o * 16 + 2 * i2 + 1]);
    }
    if (t < 16) { sb3[t] = fc3_b[t]; sb4[t] = fc4_b[t]; }

    for (int u = t; u < 2592 * 2; u += 256) {
        int arr = (u >= 2592) ? 1 : 0;
        int r   = arr ? u - 2592 : u;
        int pix = r >> 3, c2 = r & 7;
        int py = pix / 18, px = pix - py * 18;
        int hy = y0 - 1 + py, hx = x0 - 1 + px;
        float2 f = make_float2(0.f, 0.f);
        if (hy >= 0 && hy < HH && hx >= 0 && hx < WW) {
            __nv_bfloat162 h = *(const __nv_bfloat162*)
                &g_qkv[(size_t)(b * NPIX + hy * WW + hx) * 384 + arr * 64 + jbase + c2 * 2];
            f = __bfloat1622float2(h);
        }
        (arr ? hk : hq)[pix * HP + c2] = f;
    }
    __syncthreads();

    int tx = t & 15, c2 = (t >> 4) & 7, ys = t >> 7;
    int ybase = ys * 8;
    {
        unsigned long long wq2[9], wk2[9];
        #pragma unroll
        for (int tap = 0; tap < 9; tap++) {
            wq2[tap] = *(unsigned long long*)&swq[c2 * 9 + tap];
            wk2[tap] = *(unsigned long long*)&swk[c2 * 9 + tap];
        }
        unsigned long long aq[8], ak[8];
        dwconv8(hq, wq2, *(unsigned long long*)&sbq[c2], tx, c2, ybase, aq);
        dwconv8(hk, wk2, *(unsigned long long*)&sbk[c2], tx, c2, ybase, ak);
        #pragma unroll
        for (int yy = 0; yy < 8; yy++) {
            unsigned long long a = fmul2(aq[yy], ak[yy]);
            *(unsigned long long*)&abuf[((ybase + yy) * 16 + tx) * HP + c2] = a;
        }
    }
    __syncthreads();   // abuf ready; hq free

    {
        unsigned long long a2[8];
        #pragma unroll
        for (int i2 = 0; i2 < 8; i2++)
            a2[i2] = *(unsigned long long*)&abuf[t * HP + i2];

        float g1[16];
        #pragma unroll
        for (int o = 0; o < 16; o++) {
            unsigned long long acc = 0ULL;
            #pragma unroll
            for (int i2 = 0; i2 < 8; i2++)
                ffma2(acc, a2[i2], *(unsigned long long*)&sw3[o * 8 + i2]);
            float v = hadd2(acc) + sb3[o];
            g1[o] = v / (1.f + __expf(-v));            // silu
        }
        unsigned long long g2[8];
        #pragma unroll
        for (int i2 = 0; i2 < 8; i2++) g2[i2] = pack2(g1[2 * i2], g1[2 * i2 + 1]);

        #pragma unroll
        for (int o2 = 0; o2 < 8; o2++) {
            float gv[2];
            #pragma unroll
            for (int hh = 0; hh < 2; hh++) {
                int o = o2 * 2 + hh;
                unsigned long long acc = 0ULL;
                #pragma unroll
                for (int i2 = 0; i2 < 8; i2++)
                    ffma2(acc, g2[i2], *(unsigned long long*)&sw4[o * 8 + i2]);
                gv[hh] = tanhf((hadd2(acc) + sb4[o]) * 8.f);   // tanh(a / LD^-0.5)
            }
            abuf[t * HP + o2] = make_float2(gv[0], gv[1]);     // gate in place
        }
        for (int u = t; u < 2592; u += 256) {
            int pix = u >> 3, cc = u & 7;
            int py = pix / 18, px = pix - py * 18;
            int hy = y0 - 1 + py, hx = x0 - 1 + px;
            float2 f = make_float2(0.f, 0.f);
            if (hy >= 0 && hy < HH && hx >= 0 && hx < WW) {
                __nv_bfloat162 h = *(const __nv_bfloat162*)
                    &g_qkv[(size_t)(b * NPIX + hy * WW + hx) * 384 + 128 + jbase + cc * 2];
                f = __bfloat1622float2(h);
            }
            hq[pix * HP + cc] = f;
        }
    }
    __syncthreads();   // gates + v halo ready

    {
        unsigned long long wv2[9];
        #pragma unroll
        for (int tap = 0; tap < 9; tap++)
            wv2[tap] = *(unsigned long long*)&swv[c2 * 9 + tap];
        unsigned long long av[8];
        dwconv8(hq, wv2, *(unsigned long long*)&sbv[c2], tx, c2, ybase, av);
        #pragma unroll
        for (int yy = 0; yy < 8; yy++) {
            int pix = (ybase + yy) * 16 + tx;
            unsigned long long g = *(unsigned long long*)&abuf[pix * HP + c2];
            *(unsigned long long*)&hk[pix * HP + c2] = fmul2(g, av[yy]);
        }
    }
    __syncthreads();

    {
        unsigned int ow[8];
        #pragma unroll
        for (int i2 = 0; i2 < 8; i2++) {
            float2 f = hk[t * HP + i2];
            __nv_bfloat162 h = __floats2bfloat162_rn(f.x, f.y);
            ow[i2] = *(unsigned int*)&h;
        }
        int py = t >> 4, px = t & 15;
        __nv_bfloat16* dst = g_xc +
            (size_t)(b * NPIX + (y0 + py) * WW + (x0 + px)) * 128 + jbase;
        *(uint4*)dst       = make_uint4(ow[0], ow[1], ow[2], ow[3]);
        *(uint4*)(dst + 8) = make_uint4(ow[4], ow[5], ow[6], ow[7]);
    }
}

// ============================================================================
// K5: fc5 GEMM + bias + residual — TENSOR-CORE mainloop (bisect candidate).
// Block 256 (8 warps): tile 64 pix x 128 out, K=128.
// Dyn smem: At bf16 [64][136] @0 (17408B) | Wt bf16 [128][136] @17408 (34816B)
//           Cs f32 [64][133] (34048B) aliases Wt after mainloop.
// Warp w: m0=(w&3)*16, c0=(w>>2)*64.
// ============================================================================
__global__ __launch_bounds__(256) void fc5_kernel(
    const float* __restrict__ x, const float* __restrict__ fc5_w,
    const float* __restrict__ fc5_b, float* __restrict__ out)
{
    extern __shared__ char dsm[];
    __nv_bfloat16* At = (__nv_bfloat16*)dsm;            // pitch 136 bf16 (272B)
    __nv_bfloat16* Wt = (__nv_bfloat16*)(dsm + 17408);  // pitch 136 bf16
    float*         Cs = (float*)(dsm + 17408);          // pitch 133 f32
    __shared__ float sb[128];

    int t  = threadIdx.x;
    int P0 = blockIdx.x * 64;

    // stage A (bf16 copy, 16B chunks) and W (fp32 -> bf16)
    for (int v = t; v < 1024; v += 256) {
        int row = v >> 4, p = v & 15;
        uint4 d = *(const uint4*)&g_xc[(size_t)(P0 + row) * 128 + p * 8];
        *(uint4*)((char*)At + row * 272 + p * 16) = d;
    }
    for (int v = t; v < 2048; v += 256) {
        int row = v >> 4, p = v & 15;
        const float4 f0 = *(const float4*)&fc5_w[row * 128 + p * 8];
        const float4 f1 = *(const float4*)&fc5_w[row * 128 + p * 8 + 4];
        __nv_bfloat162 h0 = __floats2bfloat162_rn(f0.x, f0.y);
        __nv_bfloat162 h1 = __floats2bfloat162_rn(f0.z, f0.w);
        __nv_bfloat162 h2 = __floats2bfloat162_rn(f1.x, f1.y);
        __nv_bfloat162 h3 = __floats2bfloat162_rn(f1.z, f1.w);
        uint4 o = make_uint4(*(unsigned*)&h0, *(unsigned*)&h1,
                             *(unsigned*)&h2, *(unsigned*)&h3);
        *(uint4*)((char*)Wt + row * 272 + p * 16) = o;
    }
    if (t < 128) sb[t] = fc5_b[t];
    __syncthreads();

    int l = t & 31, w = t >> 5;
    int m0 = (w & 3) * 16, c0 = (w >> 2) * 64;

    // ldmatrix lane addressing: lanes 0-15 -> rows, lanes 16-31 -> +8 halfwords
    unsigned a_base = (unsigned)__cvta_generic_to_shared(At)
                    + ((m0 + (l & 15)) * 136 + (l >> 4) * 8) * 2;
    unsigned b_base = (unsigned)__cvta_generic_to_shared(Wt)
                    + ((c0 + (l & 15)) * 136 + (l >> 4) * 8) * 2;

    float acc[8][4];
    #pragma unroll
    for (int j = 0; j < 8; j++)
        #pragma unroll
        for (int q = 0; q < 4; q++) acc[j][q] = 0.f;

    #pragma unroll
    for (int kc = 0; kc < 8; kc++) {
        unsigned af[4];
        ldsm_x4(a_base + kc * 32, af[0], af[1], af[2], af[3]);
        #pragma unroll
        for (int nb = 0; nb < 4; nb++) {
            unsigned r0, r1, r2, r3;
            ldsm_x4(b_base + nb * 16 * 272 + kc * 32, r0, r1, r2, r3);
            mma16816(acc[nb * 2],     af, r0, r2);   // n-tile c0+nb*16 .. +7
            mma16816(acc[nb * 2 + 1], af, r1, r3);   // n-tile c0+nb*16+8 .. +15
        }
    }
    __syncthreads();   // all warps done reading Wt; safe to overwrite with Cs

    // stage C into smem (transposed readout buffer), pitch 133 floats
    {
        int colb = c0 + (l & 3) * 2;
        int row0 = m0 + (l >> 2);
        #pragma unroll
        for (int j = 0; j < 8; j++) {
            int col = colb + j * 8;
            Cs[row0 * 133 + col]           = acc[j][0];
            Cs[row0 * 133 + col + 1]       = acc[j][1];
            Cs[(row0 + 8) * 133 + col]     = acc[j][2];
            Cs[(row0 + 8) * 133 + col + 1] = acc[j][3];
        }
    }
    __syncthreads();

    // coalesced readout + bias + residual (NCHW)
    int bimg = P0 >> 12;
    int hw0  = P0 & 4095;
    int pix = t & 63, cq = t >> 6;
    #pragma unroll 4
    for (int g = 0; g < 32; g++) {
        int c = g * 4 + cq;
        size_t off = (size_t)(bimg * 128 + c) * NPIX + hw0 + pix;
        out[off] = Cs[pix * 133 + c] + sb[c] + x[off];
    }
}

// ============================================================================
extern "C" void kernel_launch(void* const* d_in, const int* in_sizes, int n_in,
                              void* d_out, int out_size)
{
    const float* x       = (const float*)d_in[0];
    const float* norm_g  = (const float*)d_in[1];
    const float* norm_b  = (const float*)d_in[2];
    const float* fc1_w   = (const float*)d_in[3];
    const float* fc1_b   = (const float*)d_in[4];
    const float* fc2_w   = (const float*)d_in[5];
    const float* fc2_b   = (const float*)d_in[6];
    const float* qconv_w = (const float*)d_in[7];
    const float* qconv_b = (const float*)d_in[8];
    const float* kconv_w = (const float*)d_in[9];
    const float* kconv_b = (const float*)d_in[10];
    const float* vconv_w = (const float*)d_in[11];
    const float* vconv_b = (const float*)d_in[12];
    const float* fc3_w   = (const float*)d_in[13];
    const float* fc3_b   = (const float*)d_in[14];
    const float* fc4_w   = (const float*)d_in[15];
    const float* fc4_b   = (const float*)d_in[16];
    const float* fc5_w   = (const float*)d_in[17];
    const float* fc5_b   = (const float*)d_in[18];

    const int LNQKV_SMEM = 16640 * 4;           // 66560 B
    const int FC5_SMEM   = 52224;               // At + Wt/Cs
    const int LOC_SMEM   = LOC_SMEM_F2 * 8;     // 65088 B
    cudaFuncSetAttribute(lnqkv_kernel, cudaFuncAttributeMaxDynamicSharedMemorySize, LNQKV_SMEM);
    cudaFuncSetAttribute(fc5_kernel,   cudaFuncAttributeMaxDynamicSharedMemorySize, FC5_SMEM);
    cudaFuncSetAttribute(local_kernel, cudaFuncAttributeMaxDynamicSharedMemorySize, LOC_SMEM);

    lnqkv_kernel<<<NP / 64, 256, LNQKV_SMEM>>>(x, norm_g, norm_b, fc1_w, fc1_b, fc2_w, fc2_b);
    pool_kernel<<<BB * 64, 128>>>();
    attn_kernel<<<dim3(BB * 4, 16), 256>>>();
    local_kernel<<<dim3(16, 4, BB), 256, LOC_SMEM>>>(qconv_w, qconv_b, kconv_w, kconv_b,
                                                     vconv_w, vconv_b, fc3_w, fc3_b,
                                                     fc4_w, fc4_b);
    fc5_kernel<<<NP / 64, 256, FC5_SMEM>>>(x, fc5_w, fc5_b, (float*)d_out);
}

// round 14
// speedup vs baseline: 2.0505x; 2.0505x over previous
#include <cuda_runtime.h>
#include <cuda_bf16.h>

// Problem constants
#define BB   32
#define HH   64
#define WW   64
#define NPIX (HH*WW)              // 4096 per image
#define NP   (BB*NPIX)            // 131072 pixels

// -------- scratch (device globals; no runtime allocation) --------
__device__ __nv_bfloat16 g_qkv[NP * 384]; // [0:192) local qkv (fc2), [192:384) global qkv (fc1)
__device__ float g_kp [BB*4*64*16];       // pooled global k
__device__ float g_vp [BB*4*64*16];       // pooled global v
__device__ __nv_bfloat16 g_xc [NP * 128]; // concat [xl | xg], pixel-major, bf16

// -------- packed fp32x2 helpers --------
__device__ __forceinline__ void ffma2(unsigned long long& d,
                                      unsigned long long a, unsigned long long b) {
    asm("fma.rn.f32x2 %0, %1, %2, %0;" : "+l"(d) : "l"(a), "l"(b));
}
__device__ __forceinline__ unsigned long long fmul2(unsigned long long a,
                                                    unsigned long long b) {
    unsigned long long r;
    asm("mul.rn.f32x2 %0, %1, %2;" : "=l"(r) : "l"(a), "l"(b));
    return r;
}
__device__ __forceinline__ unsigned long long pack2(float lo, float hi) {
    unsigned long long r;
    asm("mov.b64 %0, {%1, %2};" : "=l"(r) : "f"(lo), "f"(hi));
    return r;
}
__device__ __forceinline__ float hadd2(unsigned long long v) {
    float lo, hi;
    asm("mov.b64 {%0, %1}, %2;" : "=f"(lo), "=f"(hi) : "l"(v));
    return lo + hi;
}
__device__ __forceinline__ void unpack2(unsigned long long v, float& lo, float& hi) {
    asm("mov.b64 {%0, %1}, %2;" : "=f"(lo), "=f"(hi) : "l"(v));
}

// -------- tensor-core helpers (mma.sync bf16) — validated in round 11 --------
__device__ __forceinline__ void ldsm_x4(unsigned addr, unsigned& r0, unsigned& r1,
                                        unsigned& r2, unsigned& r3) {
    asm volatile("ldmatrix.sync.aligned.m8n8.x4.shared.b16 {%0,%1,%2,%3}, [%4];"
                 : "=r"(r0), "=r"(r1), "=r"(r2), "=r"(r3) : "r"(addr));
}
__device__ __forceinline__ void mma16816(float* c, const unsigned* a,
                                         unsigned b0, unsigned b1) {
    asm volatile(
        "mma.sync.aligned.m16n8k16.row.col.f32.bf16.bf16.f32 "
        "{%0,%1,%2,%3}, {%4,%5,%6,%7}, {%8,%9}, {%0,%1,%2,%3};"
        : "+f"(c[0]), "+f"(c[1]), "+f"(c[2]), "+f"(c[3])
        : "r"(a[0]), "r"(a[1]), "r"(a[2]), "r"(a[3]), "r"(b0), "r"(b1));
}

// ============================================================================
// K1: fused LayerNorm + qkv GEMM — TENSOR-CORE mainloop.
// Block: 64 pixels, 256 threads (8 warps).  Warp w: m0=(w&3)*16, n0=(w>>2)*32.
// Dyn smem bytes: A0 bf16 [64][72] @0 (9216) | A1 @9216 (9216) |
//                 s_raw f32 [128*65] @18432 (33280; Wt bf16 [64][72] aliases it)
// 6 weight tiles staged one at a time (same fencing as the passing FFMA2 loop).
// ============================================================================
__global__ __launch_bounds__(256) void lnqkv_kernel(
    const float* __restrict__ x, const float* __restrict__ gamma,
    const float* __restrict__ beta,
    const float* __restrict__ fc1_w, const float* __restrict__ fc1_b,
    const float* __restrict__ fc2_w, const float* __restrict__ fc2_b)
{
    extern __shared__ char dsm[];
    __nv_bfloat16* A0    = (__nv_bfloat16*)dsm;             // pitch 72 bf16 (144B)
    __nv_bfloat16* A1    = (__nv_bfloat16*)(dsm + 9216);
    float*         s_raw = (float*)(dsm + 18432);           // [c*65 + pix]
    __nv_bfloat16* Wt    = (__nv_bfloat16*)(dsm + 18432);   // alias; pitch 72
    __shared__ float smean[64], srstd[64];
    __shared__ float sb[384];

    int t    = threadIdx.x;
    int P0   = blockIdx.x * 64;
    int bimg = P0 >> 12;
    int hw0  = P0 & 4095;
    const float* xb = x + (size_t)bimg * 128 * NPIX + hw0;

    for (int idx = t; idx < 8192; idx += 256) {
        int c = idx >> 6, pix = idx & 63;
        s_raw[c * 65 + pix] = xb[c * NPIX + pix];
    }
    for (int v = t; v < 384; v += 256)
        sb[v] = (v < 192) ? fc2_b[v] : fc1_b[v - 192];
    __syncthreads();

    if (t < 64) {
        float sum = 0.f, sq = 0.f;
        #pragma unroll
        for (int c = 0; c < 128; c++) {
            float v = s_raw[c * 65 + t];
            sum += v; sq += v * v;
        }
        float m   = sum * (1.f / 128.f);
        float var = sq  * (1.f / 128.f) - m * m;
        smean[t] = m;
        srstd[t] = rsqrtf(var + 1e-5f);
    }
    __syncthreads();
    // normalize -> bf16 A tiles.  idx = pix*64 + c2: smem writes conflict-free.
    for (int idx = t; idx < 4096; idx += 256) {
        int pix = idx >> 6, c2 = idx & 63;
        int c   = c2 * 2;
        float m = smean[pix], r = srstd[pix];
        float v0 = (s_raw[c * 65 + pix]       - m) * r * gamma[c]     + beta[c];
        float v1 = (s_raw[(c + 1) * 65 + pix] - m) * r * gamma[c + 1] + beta[c + 1];
        __nv_bfloat16* A = (c2 < 32) ? A0 : A1;
        int k2 = c2 & 31;
        __nv_bfloat162 h = __floats2bfloat162_rn(v0, v1);
        *(unsigned*)&A[pix * 72 + k2 * 2] = *(unsigned*)&h;
    }
    __syncthreads();   // s_raw fully consumed; Wt may now overwrite it

    int l = t & 31, w = t >> 5;
    int m0 = (w & 3) * 16, n0 = (w >> 2) * 32;

    unsigned a0_base = (unsigned)__cvta_generic_to_shared(A0)
                     + ((m0 + (l & 15)) * 72 + (l >> 4) * 8) * 2;
    unsigned a1_base = (unsigned)__cvta_generic_to_shared(A1)
                     + ((m0 + (l & 15)) * 72 + (l >> 4) * 8) * 2;
    unsigned wt_base = (unsigned)__cvta_generic_to_shared(Wt)
                     + ((n0 + (l & 15)) * 72 + (l >> 4) * 8) * 2;

    unsigned afr[4][4];
    int cur_half = -1;

    for (int nt = 0; nt < 6; nt++) {
        int half = (nt < 3) ? 0 : 1;
        const float* W = half ? fc1_w : fc2_w;
        int wrow0 = half ? (nt - 3) * 64 : nt * 64;

        // stage weight tile (fp32 -> bf16), coalesced float2 reads
        for (int u = t; u < 2048; u += 256) {
            int j = u >> 5, kk = u & 31;
            float2 wv = *(const float2*)&W[(wrow0 + j) * 64 + kk * 2];
            __nv_bfloat162 h = __floats2bfloat162_rn(wv.x, wv.y);
            *(unsigned*)&Wt[j * 72 + kk * 2] = *(unsigned*)&h;
        }
        __syncthreads();

        if (half != cur_half) {
            unsigned ab = half ? a1_base : a0_base;
            #pragma unroll
            for (int kc = 0; kc < 4; kc++)
                ldsm_x4(ab + kc * 32, afr[kc][0], afr[kc][1], afr[kc][2], afr[kc][3]);
            cur_half = half;
        }

        float acc[4][4];
        #pragma unroll
        for (int j = 0; j < 4; j++)
            #pragma unroll
            for (int q = 0; q < 4; q++) acc[j][q] = 0.f;

        #pragma unroll
        for (int kc = 0; kc < 4; kc++) {
            #pragma unroll
            for (int nb = 0; nb < 2; nb++) {
                unsigned r0, r1, r2, r3;
                ldsm_x4(wt_base + nb * 16 * 144 + kc * 32, r0, r1, r2, r3);
                mma16816(acc[nb * 2],     afr[kc], r0, r2);
                mma16816(acc[nb * 2 + 1], afr[kc], r1, r3);
            }
        }

        // epilogue: bias + bf16 store to g_qkv
        int colb = nt * 64 + n0 + (l & 3) * 2;
        size_t row0 = (size_t)(P0 + m0 + (l >> 2));
        #pragma unroll
        for (int j = 0; j < 4; j++) {
            int col = colb + j * 8;
            float b0v = sb[col], b1v = sb[col + 1];
            __nv_bfloat162 hA = __floats2bfloat162_rn(acc[j][0] + b0v, acc[j][1] + b1v);
            __nv_bfloat162 hB = __floats2bfloat162_rn(acc[j][2] + b0v, acc[j][3] + b1v);
            *(unsigned*)&g_qkv[row0 * 384 + col]       = *(unsigned*)&hA;
            *(unsigned*)&g_qkv[(row0 + 8) * 384 + col] = *(unsigned*)&hB;
        }
        __syncthreads();   // Wt reads complete before next tile staging
    }
}

// ============================================================================
// K2: 8x8 average pooling of global k,v (bf16 in, fp32 out).
// ============================================================================
__global__ __launch_bounds__(128) void pool_kernel()
{
    int bm = blockIdx.x;
    int b  = bm >> 6, m = bm & 63;
    int ph = m >> 3,  pw = m & 7;
    int t  = threadIdx.x;
    int base = b * NPIX + ph * 8 * WW + pw * 8;
    float acc = 0.f;
    #pragma unroll 8
    for (int i = 0; i < 64; i++) {
        int dy = i >> 3, dx = i & 7;
        acc += __bfloat162float(g_qkv[(size_t)(base + dy * WW + dx) * 384 + 256 + t]);
    }
    acc *= (1.f / 64.f);
    int gh = (t & 63) >> 4, cg = t & 15;
    float* dst = (t < 64) ? g_kp : g_vp;
    dst[((b * 4 + gh) * 64 + m) * 16 + cg] = acc;
}

// ============================================================================
// K3: global attention.  (identical to 528.7us run)
// ============================================================================
__global__ __launch_bounds__(256) void attn_kernel()
{
    __shared__ __align__(16) float sk[64 * 16], sv[64 * 16];
    int b = blockIdx.x >> 2, gh = blockIdx.x & 3;
    int kvbase = ((b * 4 + gh) * 64) * 16;
    for (int idx = threadIdx.x; idx < 1024; idx += 256) {
        sk[idx] = g_kp[kvbase + idx];
        sv[idx] = g_vp[kvbase + idx];
    }
    __syncthreads();

    int n = blockIdx.y * 256 + threadIdx.x;
    size_t p = (size_t)b * NPIX + n;
    const __nv_bfloat16* qp = g_qkv + p * 384 + 192 + gh * 16;
    uint4 qa = *(const uint4*)qp;
    uint4 qb = *(const uint4*)(qp + 8);
    unsigned int qw[8] = {qa.x, qa.y, qa.z, qa.w, qb.x, qb.y, qb.z, qb.w};
    unsigned long long q2[8];
    #pragma unroll
    for (int i = 0; i < 8; i++) {
        __nv_bfloat162 h = *(__nv_bfloat162*)&qw[i];
        float2 f = __bfloat1622float2(h);
        q2[i] = pack2(f.x, f.y);
    }

    float lo[64];
    float mx = -1e30f;
    #pragma unroll
    for (int m = 0; m < 64; m++) {
        unsigned long long acc2 = 0ULL;
        #pragma unroll
        for (int c4 = 0; c4 < 4; c4++) {
            ulonglong2 kk = *(const ulonglong2*)&sk[m * 16 + c4 * 4];
            ffma2(acc2, q2[c4 * 2],     kk.x);
            ffma2(acc2, q2[c4 * 2 + 1], kk.y);
        }
        float d = hadd2(acc2) * 0.125f;
        lo[m] = d;
        mx = fmaxf(mx, d);
    }
    float s = 0.f;
    #pragma unroll
    for (int m = 0; m < 64; m++) { float e = __expf(lo[m] - mx); lo[m] = e; s += e; }
    float inv = 1.f / s;

    unsigned long long o2[8];
    #pragma unroll
    for (int c2 = 0; c2 < 8; c2++) o2[c2] = 0ULL;
    #pragma unroll
    for (int m = 0; m < 64; m++) {
        float w = lo[m] * inv;
        unsigned long long ww = pack2(w, w);
        #pragma unroll
        for (int c4 = 0; c4 < 4; c4++) {
            ulonglong2 vv = *(const ulonglong2*)&sv[m * 16 + c4 * 4];
            ffma2(o2[c4 * 2],     ww, vv.x);
            ffma2(o2[c4 * 2 + 1], ww, vv.y);
        }
    }
    unsigned int ow[8];
    #pragma unroll
    for (int c2 = 0; c2 < 8; c2++) {
        float x0, x1;
        unpack2(o2[c2], x0, x1);
        __nv_bfloat162 h = __floats2bfloat162_rn(x0, x1);
        ow[c2] = *(unsigned int*)&h;
    }
    __nv_bfloat16* dst = g_xc + p * 128 + 64 + gh * 16;
    *(uint4*)dst       = make_uint4(ow[0], ow[1], ow[2], ow[3]);
    *(uint4*)(dst + 8) = make_uint4(ow[4], ow[5], ow[6], ow[7]);
}

// ============================================================================
// K4: local branch.  (identical to 528.7us run)
// ============================================================================
#define HP 9                       // float2 pitch per halo pixel
#define HQ_OFF 0
#define HK_OFF 2916
#define AB_OFF 5832
#define LOC_SMEM_F2 8136           // total float2s

__device__ __forceinline__ void dwconv8(
    const float2* __restrict__ h, const unsigned long long* __restrict__ w2,
    unsigned long long bias2, int tx, int c2, int ybase,
    unsigned long long out[8])
{
    unsigned long long r[3][3];
    #pragma unroll
    for (int rr = 0; rr < 2; rr++)
        #pragma unroll
        for (int dx = 0; dx < 3; dx++)
            r[rr + 1][dx] = *(const unsigned long long*)
                &h[((ybase + rr) * 18 + tx + dx) * HP + c2];
    #pragma unroll
    for (int yy = 0; yy < 8; yy++) {
        #pragma unroll
        for (int dx = 0; dx < 3; dx++) { r[0][dx] = r[1][dx]; r[1][dx] = r[2][dx]; }
        #pragma unroll
        for (int dx = 0; dx < 3; dx++)
            r[2][dx] = *(const unsigned long long*)
                &h[((ybase + yy + 2) * 18 + tx + dx) * HP + c2];
        unsigned long long acc = bias2;
        #pragma unroll
        for (int dy = 0; dy < 3; dy++)
            #pragma unroll
            for (int dx = 0; dx < 3; dx++)
                ffma2(acc, r[dy][dx], w2[dy * 3 + dx]);
        out[yy] = acc;
    }
}

__global__ __launch_bounds__(256) void local_kernel(
    const float* __restrict__ qconv_w, const float* __restrict__ qconv_b,
    const float* __restrict__ kconv_w, const float* __restrict__ kconv_b,
    const float* __restrict__ vconv_w, const float* __restrict__ vconv_b,
    const float* __restrict__ fc3_w,  const float* __restrict__ fc3_b,
    const float* __restrict__ fc4_w,  const float* __restrict__ fc4_b)
{
    extern __shared__ float2 lsm[];
    float2* hq   = lsm + HQ_OFF;     // q halo; later v halo
    float2* hk   = lsm + HK_OFF;     // k halo; later output staging
    float2* abuf = lsm + AB_OFF;     // a / gate buffer, [pix*HP + c2]

    __shared__ float2 swq[72], swk[72], swv[72];     // packed dwconv weights
    __shared__ float2 sbq[8],  sbk[8],  sbv[8];
    __shared__ float2 sw3[128], sw4[128];            // fc3/fc4 packed over input pairs
    __shared__ float  sb3[16],  sb4[16];

    int t    = threadIdx.x;
    int tile = blockIdx.x, lh = blockIdx.y, b = blockIdx.z;
    int y0 = (tile >> 2) * 16, x0 = (tile & 3) * 16;
    int jbase = lh * 16;

    for (int u = t; u < 72; u += 256) {
        int c2 = u / 9, tap = u - c2 * 9;
        swq[u] = make_float2(qconv_w[(2 * c2) * 9 + tap], qconv_w[(2 * c2 + 1) * 9 + tap]);
        swk[u] = make_float2(kconv_w[(2 * c2) * 9 + tap], kconv_w[(2 * c2 + 1) * 9 + tap]);
        swv[u] = make_float2(vconv_w[(2 * c2) * 9 + tap], vconv_w[(2 * c2 + 1) * 9 + tap]);
    }
    if (t < 8) {
        sbq[t] = make_float2(qconv_b[2 * t], qconv_b[2 * t + 1]);
        sbk[t] = make_float2(kconv_b[2 * t], kconv_b[2 * t + 1]);
        sbv[t] = make_float2(vconv_b[2 * t], vconv_b[2 * t + 1]);
    }
    for (int u = t; u < 128; u += 256) {
        int o = u >> 3, i2 = u & 7;
        sw3[u] = make_float2(fc3_w[o * 16 + 2 * i2], fc3_w[o * 16 + 2 * i2 + 1]);
        sw4[u] = make_float2(fc4_w[o * 16 + 2 * i2], fc4_w[o * 16 + 2 * i2 + 1]);
    }
    if (t < 16) { sb3[t] = fc3_b[t]; sb4[t] = fc4_b[t]; }

    for (int u = t; u < 2592 * 2; u += 256) {
        int arr = (u >= 2592) ? 1 : 0;
        int r   = arr ? u - 2592 : u;
        int pix = r >> 3, c2 = r & 7;
        int py = pix / 18, px = pix - py * 18;
        int hy = y0 - 1 + py, hx = x0 - 1 + px;
        float2 f = make_float2(0.f, 0.f);
        if (hy >= 0 && hy < HH && hx >= 0 && hx < WW) {
            __nv_bfloat162 h = *(const __nv_bfloat162*)
                &g_qkv[(size_t)(b * NPIX + hy * WW + hx) * 384 + arr * 64 + jbase + c2 * 2];
            f = __bfloat1622float2(h);
        }
        (arr ? hk : hq)[pix * HP + c2] = f;
    }
    __syncthreads();

    int tx = t & 15, c2 = (t >> 4) & 7, ys = t >> 7;
    int ybase = ys * 8;
    {
        unsigned long long wq2[9], wk2[9];
        #pragma unroll
        for (int tap = 0; tap < 9; tap++) {
            wq2[tap] = *(unsigned long long*)&swq[c2 * 9 + tap];
            wk2[tap] = *(unsigned long long*)&swk[c2 * 9 + tap];
        }
        unsigned long long aq[8], ak[8];
        dwconv8(hq, wq2, *(unsigned long long*)&sbq[c2], tx, c2, ybase, aq);
        dwconv8(hk, wk2, *(unsigned long long*)&sbk[c2], tx, c2, ybase, ak);
        #pragma unroll
        for (int yy = 0; yy < 8; yy++) {
            unsigned long long a = fmul2(aq[yy], ak[yy]);
            *(unsigned long long*)&abuf[((ybase + yy) * 16 + tx) * HP + c2] = a;
        }
    }
    __syncthreads();   // abuf ready; hq free

    {
        unsigned long long a2[8];
        #pragma unroll
        for (int i2 = 0; i2 < 8; i2++)
            a2[i2] = *(unsigned long long*)&abuf[t * HP + i2];

        float g1[16];
        #pragma unroll
        for (int o = 0; o < 16; o++) {
            unsigned long long acc = 0ULL;
            #pragma unroll
            for (int i2 = 0; i2 < 8; i2++)
                ffma2(acc, a2[i2], *(unsigned long long*)&sw3[o * 8 + i2]);
            float v = hadd2(acc) + sb3[o];
            g1[o] = v / (1.f + __expf(-v));            // silu
        }
        unsigned long long g2[8];
        #pragma unroll
        for (int i2 = 0; i2 < 8; i2++) g2[i2] = pack2(g1[2 * i2], g1[2 * i2 + 1]);

        #pragma unroll
        for (int o2 = 0; o2 < 8; o2++) {
            float gv[2];
            #pragma unroll
            for (int hh = 0; hh < 2; hh++) {
                int o = o2 * 2 + hh;
                unsigned long long acc = 0ULL;
                #pragma unroll
                for (int i2 = 0; i2 < 8; i2++)
                    ffma2(acc, g2[i2], *(unsigned long long*)&sw4[o * 8 + i2]);
                gv[hh] = tanhf((hadd2(acc) + sb4[o]) * 8.f);   // tanh(a / LD^-0.5)
            }
            abuf[t * HP + o2] = make_float2(gv[0], gv[1]);     // gate in place
        }
        for (int u = t; u < 2592; u += 256) {
            int pix = u >> 3, cc = u & 7;
            int py = pix / 18, px = pix - py * 18;
            int hy = y0 - 1 + py, hx = x0 - 1 + px;
            float2 f = make_float2(0.f, 0.f);
            if (hy >= 0 && hy < HH && hx >= 0 && hx < WW) {
                __nv_bfloat162 h = *(const __nv_bfloat162*)
                    &g_qkv[(size_t)(b * NPIX + hy * WW + hx) * 384 + 128 + jbase + cc * 2];
                f = __bfloat1622float2(h);
            }
            hq[pix * HP + cc] = f;
        }
    }
    __syncthreads();   // gates + v halo ready

    {
        unsigned long long wv2[9];
        #pragma unroll
        for (int tap = 0; tap < 9; tap++)
            wv2[tap] = *(unsigned long long*)&swv[c2 * 9 + tap];
        unsigned long long av[8];
        dwconv8(hq, wv2, *(unsigned long long*)&sbv[c2], tx, c2, ybase, av);
        #pragma unroll
        for (int yy = 0; yy < 8; yy++) {
            int pix = (ybase + yy) * 16 + tx;
            unsigned long long g = *(unsigned long long*)&abuf[pix * HP + c2];
            *(unsigned long long*)&hk[pix * HP + c2] = fmul2(g, av[yy]);
        }
    }
    __syncthreads();

    {
        unsigned int ow[8];
        #pragma unroll
        for (int i2 = 0; i2 < 8; i2++) {
            float2 f = hk[t * HP + i2];
            __nv_bfloat162 h = __floats2bfloat162_rn(f.x, f.y);
            ow[i2] = *(unsigned int*)&h;
        }
        int py = t >> 4, px = t & 15;
        __nv_bfloat16* dst = g_xc +
            (size_t)(b * NPIX + (y0 + py) * WW + (x0 + px)) * 128 + jbase;
        *(uint4*)dst       = make_uint4(ow[0], ow[1], ow[2], ow[3]);
        *(uint4*)(dst + 8) = make_uint4(ow[4], ow[5], ow[6], ow[7]);
    }
}

// ============================================================================
// K5: fc5 GEMM + bias + residual — tensor-core (identical to round-11 pass).
// ============================================================================
__global__ __launch_bounds__(256) void fc5_kernel(
    const float* __restrict__ x, const float* __restrict__ fc5_w,
    const float* __restrict__ fc5_b, float* __restrict__ out)
{
    extern __shared__ char dsm[];
    __nv_bfloat16* At = (__nv_bfloat16*)dsm;            // pitch 136 bf16 (272B)
    __nv_bfloat16* Wt = (__nv_bfloat16*)(dsm + 17408);  // pitch 136 bf16
    float*         Cs = (float*)(dsm + 17408);          // pitch 133 f32
    __shared__ float sb[128];

    int t  = threadIdx.x;
    int P0 = blockIdx.x * 64;

    for (int v = t; v < 1024; v += 256) {
        int row = v >> 4, p = v & 15;
        uint4 d = *(const uint4*)&g_xc[(size_t)(P0 + row) * 128 + p * 8];
        *(uint4*)((char*)At + row * 272 + p * 16) = d;
    }
    for (int v = t; v < 2048; v += 256) {
        int row = v >> 4, p = v & 15;
        const float4 f0 = *(const float4*)&fc5_w[row * 128 + p * 8];
        const float4 f1 = *(const float4*)&fc5_w[row * 128 + p * 8 + 4];
        __nv_bfloat162 h0 = __floats2bfloat162_rn(f0.x, f0.y);
        __nv_bfloat162 h1 = __floats2bfloat162_rn(f0.z, f0.w);
        __nv_bfloat162 h2 = __floats2bfloat162_rn(f1.x, f1.y);
        __nv_bfloat162 h3 = __floats2bfloat162_rn(f1.z, f1.w);
        uint4 o = make_uint4(*(unsigned*)&h0, *(unsigned*)&h1,
                             *(unsigned*)&h2, *(unsigned*)&h3);
        *(uint4*)((char*)Wt + row * 272 + p * 16) = o;
    }
    if (t < 128) sb[t] = fc5_b[t];
    __syncthreads();

    int l = t & 31, w = t >> 5;
    int m0 = (w & 3) * 16, c0 = (w >> 2) * 64;

    unsigned a_base = (unsigned)__cvta_generic_to_shared(At)
                    + ((m0 + (l & 15)) * 136 + (l >> 4) * 8) * 2;
    unsigned b_base = (unsigned)__cvta_generic_to_shared(Wt)
                    + ((c0 + (l & 15)) * 136 + (l >> 4) * 8) * 2;

    float acc[8][4];
    #pragma unroll
    for (int j = 0; j < 8; j++)
        #pragma unroll
        for (int q = 0; q < 4; q++) acc[j][q] = 0.f;

    #pragma unroll
    for (int kc = 0; kc < 8; kc++) {
        unsigned af[4];
        ldsm_x4(a_base + kc * 32, af[0], af[1], af[2], af[3]);
        #pragma unroll
        for (int nb = 0; nb < 4; nb++) {
            unsigned r0, r1, r2, r3;
            ldsm_x4(b_base + nb * 16 * 272 + kc * 32, r0, r1, r2, r3);
            mma16816(acc[nb * 2],     af, r0, r2);
            mma16816(acc[nb * 2 + 1], af, r1, r3);
        }
    }
    __syncthreads();   // all warps done reading Wt; safe to overwrite with Cs

    {
        int colb = c0 + (l & 3) * 2;
        int row0 = m0 + (l >> 2);
        #pragma unroll
        for (int j = 0; j < 8; j++) {
            int col = colb + j * 8;
            Cs[row0 * 133 + col]           = acc[j][0];
            Cs[row0 * 133 + col + 1]       = acc[j][1];
            Cs[(row0 + 8) * 133 + col]     = acc[j][2];
            Cs[(row0 + 8) * 133 + col + 1] = acc[j][3];
        }
    }
    __syncthreads();

    int bimg = P0 >> 12;
    int hw0  = P0 & 4095;
    int pix = t & 63, cq = t >> 6;
    #pragma unroll 4
    for (int g = 0; g < 32; g++) {
        int c = g * 4 + cq;
        size_t off = (size_t)(bimg * 128 + c) * NPIX + hw0 + pix;
        out[off] = Cs[pix * 133 + c] + sb[c] + x[off];
    }
}

// ============================================================================
extern "C" void kernel_launch(void* const* d_in, const int* in_sizes, int n_in,
                              void* d_out, int out_size)
{
    const float* x       = (const float*)d_in[0];
    const float* norm_g  = (const float*)d_in[1];
    const float* norm_b  = (const float*)d_in[2];
    const float* fc1_w   = (const float*)d_in[3];
    const float* fc1_b   = (const float*)d_in[4];
    const float* fc2_w   = (const float*)d_in[5];
    const float* fc2_b   = (const float*)d_in[6];
    const float* qconv_w = (const float*)d_in[7];
    const float* qconv_b = (const float*)d_in[8];
    const float* kconv_w = (const float*)d_in[9];
    const float* kconv_b = (const float*)d_in[10];
    const float* vconv_w = (const float*)d_in[11];
    const float* vconv_b = (const float*)d_in[12];
    const float* fc3_w   = (const float*)d_in[13];
    const float* fc3_b   = (const float*)d_in[14];
    const float* fc4_w   = (const float*)d_in[15];
    const float* fc4_b   = (const float*)d_in[16];
    const float* fc5_w   = (const float*)d_in[17];
    const float* fc5_b   = (const float*)d_in[18];

    const int LNQKV_SMEM = 51712;               // A0 + A1 + s_raw/Wt
    const int FC5_SMEM   = 52224;               // At + Wt/Cs
    const int LOC_SMEM   = LOC_SMEM_F2 * 8;     // 65088 B
    cudaFuncSetAttribute(lnqkv_kernel, cudaFuncAttributeMaxDynamicSharedMemorySize, LNQKV_SMEM);
    cudaFuncSetAttribute(fc5_kernel,   cudaFuncAttributeMaxDynamicSharedMemorySize, FC5_SMEM);
    cudaFuncSetAttribute(local_kernel, cudaFuncAttributeMaxDynamicSharedMemorySize, LOC_SMEM);

    lnqkv_kernel<<<NP / 64, 256, LNQKV_SMEM>>>(x, norm_g, norm_b, fc1_w, fc1_b, fc2_w, fc2_b);
    pool_kernel<<<BB * 64, 128>>>();
    attn_kernel<<<dim3(BB * 4, 16), 256>>>();
    local_kernel<<<dim3(16, 4, BB), 256, LOC_SMEM>>>(qconv_w, qconv_b, kconv_w, kconv_b,
                                                     vconv_w, vconv_b, fc3_w, fc3_b,
                                                     fc4_w, fc4_b);
    fc5_kernel<<<NP / 64, 256, FC5_SMEM>>>(x, fc5_w, fc5_b, (float*)d_out);
}